// round 13
// baseline (speedup 1.0000x reference)
#include <cuda_runtime.h>
#include <cuda_bf16.h>
#include <math.h>
#include <stdint.h>

// Problem constants
#define BB 2
#define SS 2048
#define DD 1024
#define HH 16
#define DH 64

#define LOG2E 1.4426950408889634f

// ---------------- scratch (static device globals; no allocation) -------------
__device__ float g_qs[BB * HH * SS * DH];                     // 16 MB
__device__ __nv_bfloat16 g_kh[BB * HH * SS * DH];             // 8 MB
__device__ __nv_bfloat16 g_kl[BB * HH * SS * DH];             // 8 MB
__device__ __nv_bfloat16 g_vh[BB * HH * SS * DH];             // 8 MB
__device__ __nv_bfloat16 g_vl[BB * HH * SS * DH];             // 8 MB
__device__ __nv_bfloat16 g_bt[(size_t)BB * HH * SS * SS];     // 268 MB
__device__ float g_ao[BB * SS * DD];                          // 16 MB
__device__ int   g_mask_kind;                                 // 0=u8, 1=i32, 2=f32

// ---------------- mask dtype detection (parallel) -----------------------------
__global__ void detect_mask_kind_kernel(const unsigned int* __restrict__ m) {
    __shared__ int f[2];
    const int t = threadIdx.x;
    if (t < 2) f[t] = 0;
    __syncthreads();
    bool sawFloat = false, sawBig = false;
#pragma unroll
    for (int j = 0; j < 4; j++) {
        unsigned int w = m[t * 4 + j];
        if (w == 0x3F800000u) sawFloat = true;
        else if (w > 1u) sawBig = true;
    }
    if (sawFloat) atomicOr(&f[0], 1);
    if (sawBig)   atomicOr(&f[1], 1);
    __syncthreads();
    if (t == 0) g_mask_kind = f[0] ? 2 : (f[1] ? 0 : 1);
}

__device__ __forceinline__ bool mask_at(const void* mask, int kind, int idx) {
    if (kind == 0) return ((const unsigned char*)mask)[idx] != 0;
    if (kind == 1) return ((const int*)mask)[idx] != 0;
    return ((const float*)mask)[idx] != 0.0f;
}

// ---------------- bf16-split helpers -----------------------------------------
__device__ __forceinline__ void split1(float x, __nv_bfloat16& h, __nv_bfloat16& l) {
    h = __float2bfloat16_rn(x);
    l = __float2bfloat16_rn(x - __bfloat162float(h));
}

__device__ __forceinline__ void splitpack(float x, float y, uint32_t& hi, uint32_t& lo) {
    __nv_bfloat16 hx, lx, hy, ly;
    split1(x, hx, lx);
    split1(y, hy, ly);
    __nv_bfloat162 H = __halves2bfloat162(hx, hy);
    __nv_bfloat162 L = __halves2bfloat162(lx, ly);
    hi = *reinterpret_cast<uint32_t*>(&H);
    lo = *reinterpret_cast<uint32_t*>(&L);
}

__device__ __forceinline__ void mma_bf16(float c[4], const uint32_t a[4],
                                         uint32_t b0, uint32_t b1) {
    asm volatile(
        "mma.sync.aligned.m16n8k16.row.col.f32.bf16.bf16.f32 "
        "{%0,%1,%2,%3}, {%4,%5,%6,%7}, {%8,%9}, {%0,%1,%2,%3};"
        : "+f"(c[0]), "+f"(c[1]), "+f"(c[2]), "+f"(c[3])
        : "r"(a[0]), "r"(a[1]), "r"(a[2]), "r"(a[3]), "r"(b0), "r"(b1));
}

__device__ __forceinline__ void ldsm_x2_trans(uint32_t& r0, uint32_t& r1, const void* p) {
    uint32_t a = (uint32_t)__cvta_generic_to_shared(p);
    asm volatile("ldmatrix.sync.aligned.m8n8.x2.trans.shared.b16 {%0,%1}, [%2];"
                 : "=r"(r0), "=r"(r1) : "r"(a));
}

__device__ __forceinline__ void ldsm_x4(uint32_t& r0, uint32_t& r1, uint32_t& r2,
                                        uint32_t& r3, const void* p) {
    uint32_t a = (uint32_t)__cvta_generic_to_shared(p);
    asm volatile("ldmatrix.sync.aligned.m8n8.x4.shared.b16 {%0,%1,%2,%3}, [%4];"
                 : "=r"(r0), "=r"(r1), "=r"(r2), "=r"(r3) : "r"(a));
}

#define CP_ASYNC16(dst_u32, src_ptr) \
    asm volatile("cp.async.ca.shared.global [%0], [%1], 16;" \
                 :: "r"(dst_u32), "l"(src_ptr))
#define CP_COMMIT() asm volatile("cp.async.commit_group;")
#define CP_WAIT(N)  asm volatile("cp.async.wait_group %0;" :: "n"(N))

// ---------------- tensor-core GEMM: C = A[M,K] @ B[K,N] + bias[N] ------------
// R8-verified config: 128 threads (4 warps, 2x2), CTA tile 64x128, BK=32.
// mode 0: plain epilogue (writes C fp32).
// mode 1: qkv-fused epilogue — applies bias, RoPE on q/k, hi/lo split of k/v,
//         and writes g_qs / g_kh,g_kl / g_vh,g_vl directly (C unused).
__global__ __launch_bounds__(128) void mma_gemm_bias_kernel(
    const float* __restrict__ A, const float* __restrict__ B,
    const float* __restrict__ bias, float* __restrict__ C,
    int M, int N, int K, int mode)
{
    __shared__ __align__(16) __nv_bfloat16 Ah[64][40];
    __shared__ __align__(16) __nv_bfloat16 Al[64][40];
    __shared__ __align__(16) __nv_bfloat16 Bh[32][136];
    __shared__ __align__(16) __nv_bfloat16 Bl[32][136];

    const int t = threadIdx.x, w = t >> 5, lane = t & 31;
    const int wm = (w & 1) * 32, wn = (w >> 1) * 64;
    const int row0 = blockIdx.y * 64, col0 = blockIdx.x * 128;

    float acc[2][8][4];
#pragma unroll
    for (int mf = 0; mf < 2; mf++)
#pragma unroll
        for (int nf = 0; nf < 8; nf++)
#pragma unroll
            for (int r = 0; r < 4; r++) acc[mf][nf][r] = 0.f;

    const int ar = t >> 1, ac = (t & 1) * 16;
    const int br = t >> 4, bc = (t & 15) * 8;
    const float* Ag = A + (size_t)(row0 + ar) * K + ac;
    const float* Bg = B + (size_t)br * N + col0 + bc;

    float4 ra[4], rb[8];
#pragma unroll
    for (int i = 0; i < 4; i++) ra[i] = *(const float4*)(Ag + i * 4);
#pragma unroll
    for (int rr = 0; rr < 4; rr++) {
        rb[rr * 2 + 0] = *(const float4*)(Bg + (size_t)(rr * 8) * N);
        rb[rr * 2 + 1] = *(const float4*)(Bg + (size_t)(rr * 8) * N + 4);
    }

    for (int k0 = 0; k0 < K; k0 += 32) {
        {
            __nv_bfloat16 hb[16], lb[16];
            const float* f = (const float*)ra;
#pragma unroll
            for (int j = 0; j < 16; j++) split1(f[j], hb[j], lb[j]);
            *(uint4*)&Ah[ar][ac]     = *(uint4*)&hb[0];
            *(uint4*)&Ah[ar][ac + 8] = *(uint4*)&hb[8];
            *(uint4*)&Al[ar][ac]     = *(uint4*)&lb[0];
            *(uint4*)&Al[ar][ac + 8] = *(uint4*)&lb[8];
            f = (const float*)rb;
#pragma unroll
            for (int rr = 0; rr < 4; rr++) {
                __nv_bfloat16 h8[8], l8[8];
#pragma unroll
                for (int j = 0; j < 8; j++) split1(f[rr * 8 + j], h8[j], l8[j]);
                *(uint4*)&Bh[rr * 8 + br][bc] = *(uint4*)&h8[0];
                *(uint4*)&Bl[rr * 8 + br][bc] = *(uint4*)&l8[0];
            }
        }
        __syncthreads();

        if (k0 + 32 < K) {
#pragma unroll
            for (int i = 0; i < 4; i++)
                ra[i] = *(const float4*)(Ag + (k0 + 32) + i * 4);
#pragma unroll
            for (int rr = 0; rr < 4; rr++) {
                rb[rr * 2 + 0] = *(const float4*)(Bg + (size_t)(k0 + 32 + rr * 8) * N);
                rb[rr * 2 + 1] = *(const float4*)(Bg + (size_t)(k0 + 32 + rr * 8) * N + 4);
            }
        }

#pragma unroll
        for (int ks = 0; ks < 2; ks++) {
            const int kk = ks * 16;
            uint32_t a_h[2][4], a_l[2][4];
#pragma unroll
            for (int mf = 0; mf < 2; mf++) {
                const int r = wm + mf * 16 + (lane & 15);
                const int c = kk + (lane >> 4) * 8;
                ldsm_x4(a_h[mf][0], a_h[mf][1], a_h[mf][2], a_h[mf][3], &Ah[r][c]);
                ldsm_x4(a_l[mf][0], a_l[mf][1], a_l[mf][2], a_l[mf][3], &Al[r][c]);
            }
#pragma unroll
            for (int nf = 0; nf < 8; nf++) {
                const int krow = kk + (lane & 15);
                const int nc = wn + nf * 8;
                uint32_t bh0, bh1, bl0, bl1;
                ldsm_x2_trans(bh0, bh1, &Bh[krow][nc]);
                ldsm_x2_trans(bl0, bl1, &Bl[krow][nc]);
#pragma unroll
                for (int mf = 0; mf < 2; mf++) {
                    mma_bf16(acc[mf][nf], a_h[mf], bh0, bh1);
                    mma_bf16(acc[mf][nf], a_h[mf], bl0, bl1);
                    mma_bf16(acc[mf][nf], a_l[mf], bh0, bh1);
                }
            }
        }
        __syncthreads();
    }

    if (mode == 0) {
        // plain epilogue: +bias, write fp32
#pragma unroll
        for (int mf = 0; mf < 2; mf++) {
#pragma unroll
            for (int nf = 0; nf < 8; nf++) {
                const int r = row0 + wm + mf * 16 + (lane >> 2);
                const int c = col0 + wn + nf * 8 + (lane & 3) * 2;
                const float bx = bias[c], by = bias[c + 1];
                float2 o0 = make_float2(acc[mf][nf][0] + bx, acc[mf][nf][1] + by);
                float2 o1 = make_float2(acc[mf][nf][2] + bx, acc[mf][nf][3] + by);
                *(float2*)&C[(size_t)r * N + c] = o0;
                *(float2*)&C[(size_t)(r + 8) * N + c] = o1;
            }
        }
        return;
    }

    // ---- fused qkv epilogue: bias + RoPE + head-split + hi/lo split ----
    // This warp's 64 cols = one full head; pairs (j, j+32) live in nf / nf+4.
    const int Cbase = col0 + wn;            // multiple of 64
    const int type = Cbase >> 10;           // 0=q, 1=k, 2=v
    const int h = (Cbase & 1023) >> 6;      // head

    // rotation scales per j (depends only on nf, lane)
    float rsc[8];
#pragma unroll
    for (int nf = 0; nf < 4; nf++) {
        const int j0 = nf * 8 + (lane & 3) * 2;
        rsc[nf * 2 + 0] = 1.0f / powf(10000.0f, (float)(2 * j0) / 64.0f);
        rsc[nf * 2 + 1] = 1.0f / powf(10000.0f, (float)(2 * (j0 + 1)) / 64.0f);
    }

#pragma unroll
    for (int mf = 0; mf < 2; mf++) {
#pragma unroll
        for (int rr = 0; rr < 2; rr++) {
            const int r = row0 + wm + mf * 16 + (lane >> 2) + rr * 8;
            const int bb = r >> 11, s = r & 2047;
            const size_t ob = ((size_t)(bb * HH + h) * SS + s) * DH;
#pragma unroll
            for (int nf = 0; nf < 4; nf++) {
                const int j0 = nf * 8 + (lane & 3) * 2;      // dh in [0,32)
                float x1a = acc[mf][nf][rr * 2 + 0]     + bias[Cbase + j0];
                float x1b = acc[mf][nf][rr * 2 + 1]     + bias[Cbase + j0 + 1];
                float x2a = acc[mf][nf + 4][rr * 2 + 0] + bias[Cbase + j0 + 32];
                float x2b = acc[mf][nf + 4][rr * 2 + 1] + bias[Cbase + j0 + 33];

                if (type == 2) {
                    uint32_t hi, lo;
                    splitpack(x1a, x1b, hi, lo);
                    *(uint32_t*)&g_vh[ob + j0] = hi;
                    *(uint32_t*)&g_vl[ob + j0] = lo;
                    splitpack(x2a, x2b, hi, lo);
                    *(uint32_t*)&g_vh[ob + j0 + 32] = hi;
                    *(uint32_t*)&g_vl[ob + j0 + 32] = lo;
                } else {
                    const float a0 = (float)s * rsc[nf * 2 + 0];
                    const float a1 = (float)s * rsc[nf * 2 + 1];
                    const float c0 = cosf(a0), s0 = sinf(a0);
                    const float c1 = cosf(a1), s1 = sinf(a1);
                    const float o1a = x1a * c0 - x2a * s0;
                    const float o2a = x2a * c0 + x1a * s0;
                    const float o1b = x1b * c1 - x2b * s1;
                    const float o2b = x2b * c1 + x1b * s1;
                    if (type == 0) {
                        *(float2*)&g_qs[ob + j0]      = make_float2(o1a, o1b);
                        *(float2*)&g_qs[ob + j0 + 32] = make_float2(o2a, o2b);
                    } else {
                        uint32_t hi, lo;
                        splitpack(o1a, o1b, hi, lo);
                        *(uint32_t*)&g_kh[ob + j0] = hi;
                        *(uint32_t*)&g_kl[ob + j0] = lo;
                        splitpack(o2a, o2b, hi, lo);
                        *(uint32_t*)&g_kh[ob + j0 + 32] = hi;
                        *(uint32_t*)&g_kl[ob + j0 + 32] = lo;
                    }
                }
            }
        }
    }
}

// ---------------- bias transpose + mask -> bf16 (no smem) --------------------
__global__ __launch_bounds__(256) void biast3_kernel(
    const float* __restrict__ bias, const void* __restrict__ mask)
{
    const int b = blockIdx.z, q = blockIdx.y;
    const int k0 = (blockIdx.x * 256 + threadIdx.x) * 2;
    const float* src = bias + (((size_t)(b * SS + q)) * SS + k0) * HH;
    const int kind = g_mask_kind;
    const bool m0 = mask_at(mask, kind, b * SS + k0);
    const bool m1 = mask_at(mask, kind, b * SS + k0 + 1);

    float f[32];
#pragma unroll
    for (int i = 0; i < 8; i++) *(float4*)&f[i * 4] = ((const float4*)src)[i];

    const __nv_bfloat16 NINF = __float2bfloat16(-INFINITY);
    const size_t outbase = ((size_t)b * HH * SS + q) * SS + k0;
#pragma unroll
    for (int h = 0; h < HH; h++) {
        __nv_bfloat162 pk;
        pk.x = m0 ? __float2bfloat16(f[h]) : NINF;
        pk.y = m1 ? __float2bfloat16(f[16 + h]) : NINF;
        *(__nv_bfloat162*)&g_bt[outbase + (size_t)h * SS * SS] = pk;
    }
}

// ---------------- fused flash attention --------------------------------------
// 128 threads (4 warps), q-tile 64, smem 73728 -> 3 CTAs/SM (reg-capped),
// cp.async double-buffered, K frags via ldmatrix.x4, fixed-base softmax.
#define TILE_BUF 9216
#define OFF_KH 0
#define OFF_KL 18432
#define OFF_VH 36864
#define OFF_VL 55296
#define FLASH_SMEM 73728

__global__ __launch_bounds__(128, 3) void flash_kernel() {
    extern __shared__ __align__(16) char sm[];
    const uint32_t smem_base = (uint32_t)__cvta_generic_to_shared(sm);

    const int bh = blockIdx.y;
    const int b = bh >> 4, h = bh & 15;
    const int q0 = blockIdx.x * 64;
    const int t = threadIdx.x;
    const int w = t >> 5, lane = t & 31;
    const int l4 = lane >> 2, lm4 = lane & 3;

    const float* Qg = g_qs + (size_t)bh * SS * DH;
    const __nv_bfloat16* Khg = g_kh + (size_t)bh * SS * DH;
    const __nv_bfloat16* Klg = g_kl + (size_t)bh * SS * DH;
    const __nv_bfloat16* Vhg = g_vh + (size_t)bh * SS * DH;
    const __nv_bfloat16* Vlg = g_vl + (size_t)bh * SS * DH;
    const __nv_bfloat16* Bt = g_bt + (size_t)bh * SS * SS;

    const int qrow = q0 + w * 16 + l4;

    const int cr0 = t >> 3, cc = (t & 7) * 8;

#define COPY_TILE(kt, buf)                                                          \
    {                                                                               \
        const int kb = (kt) * 64;                                                   \
        _Pragma("unroll")                                                           \
        for (int ii = 0; ii < 4; ii++) {                                            \
            const int r = cr0 + ii * 16;                                            \
            const uint32_t d = smem_base + (buf) * TILE_BUF + r * 144 + cc * 2;     \
            CP_ASYNC16(d + OFF_KH, Khg + (size_t)(kb + r) * DH + cc);               \
            CP_ASYNC16(d + OFF_KL, Klg + (size_t)(kb + r) * DH + cc);               \
            CP_ASYNC16(d + OFF_VH, Vhg + (size_t)(kb + r) * DH + cc);               \
            CP_ASYNC16(d + OFF_VL, Vlg + (size_t)(kb + r) * DH + cc);               \
        }                                                                           \
        CP_COMMIT();                                                                \
    }

    uint32_t aQh[4][4], aQl[4][4];
#pragma unroll
    for (int kc = 0; kc < 4; kc++) {
        const int c0 = kc * 16 + 2 * lm4;
        float2 x0 = *(const float2*)&Qg[(size_t)qrow * DH + c0];
        float2 x1 = *(const float2*)&Qg[(size_t)(qrow + 8) * DH + c0];
        float2 x2 = *(const float2*)&Qg[(size_t)qrow * DH + c0 + 8];
        float2 x3 = *(const float2*)&Qg[(size_t)(qrow + 8) * DH + c0 + 8];
        splitpack(x0.x * 0.125f, x0.y * 0.125f, aQh[kc][0], aQl[kc][0]);
        splitpack(x1.x * 0.125f, x1.y * 0.125f, aQh[kc][1], aQl[kc][1]);
        splitpack(x2.x * 0.125f, x2.y * 0.125f, aQh[kc][2], aQl[kc][2]);
        splitpack(x3.x * 0.125f, x3.y * 0.125f, aQh[kc][3], aQl[kc][3]);
    }

    COPY_TILE(0, 0);

    float l0 = 0.f, l1 = 0.f;
    float O[8][4];
#pragma unroll
    for (int nt = 0; nt < 8; nt++)
#pragma unroll
        for (int j = 0; j < 4; j++) O[nt][j] = 0.f;

    for (int kt = 0; kt < SS / 64; kt++) {
        const int buf = kt & 1;
        const int k0 = kt * 64;
        if (kt + 1 < SS / 64) {
            COPY_TILE(kt + 1, buf ^ 1);
            CP_WAIT(1);
        } else {
            CP_WAIT(0);
        }
        __syncthreads();

        const __nv_bfloat16* sKh = (const __nv_bfloat16*)(sm + OFF_KH) + buf * 4608;
        const __nv_bfloat16* sKl = (const __nv_bfloat16*)(sm + OFF_KL) + buf * 4608;
        const __nv_bfloat16* sVh = (const __nv_bfloat16*)(sm + OFF_VH) + buf * 4608;
        const __nv_bfloat16* sVl = (const __nv_bfloat16*)(sm + OFF_VL) + buf * 4608;

        // ---- S = bias (global, latency hidden by 3 CTAs); S += (Q/8)@K^T ----
        float c_[8][4];
#pragma unroll
        for (int nt = 0; nt < 8; nt++) {
            const int kc0 = k0 + nt * 8 + 2 * lm4;
            __nv_bfloat162 b01 = *(const __nv_bfloat162*)&Bt[(size_t)qrow * SS + kc0];
            __nv_bfloat162 b23 = *(const __nv_bfloat162*)&Bt[(size_t)(qrow + 8) * SS + kc0];
            c_[nt][0] = __bfloat162float(b01.x); c_[nt][1] = __bfloat162float(b01.y);
            c_[nt][2] = __bfloat162float(b23.x); c_[nt][3] = __bfloat162float(b23.y);
        }
#pragma unroll
        for (int nt = 0; nt < 8; nt++) {
            const int krow = nt * 8 + (lane & 7);
            const int csel = (lane >> 3) * 8;
            uint32_t kh[8], kl[8];
            ldsm_x4(kh[0], kh[1], kh[2], kh[3], &sKh[krow * 72 + csel]);
            ldsm_x4(kh[4], kh[5], kh[6], kh[7], &sKh[krow * 72 + 32 + csel]);
            ldsm_x4(kl[0], kl[1], kl[2], kl[3], &sKl[krow * 72 + csel]);
            ldsm_x4(kl[4], kl[5], kl[6], kl[7], &sKl[krow * 72 + 32 + csel]);
#pragma unroll
            for (int kc = 0; kc < 4; kc++) {
                mma_bf16(c_[nt], aQh[kc], kh[2 * kc], kh[2 * kc + 1]);
                mma_bf16(c_[nt], aQh[kc], kl[2 * kc], kl[2 * kc + 1]);
                mma_bf16(c_[nt], aQl[kc], kh[2 * kc], kh[2 * kc + 1]);
            }
        }

        // ---- fixed-base softmax ----
#pragma unroll
        for (int nt = 0; nt < 8; nt++) {
            float p0 = exp2f(c_[nt][0] * LOG2E);
            float p1 = exp2f(c_[nt][1] * LOG2E);
            float p2 = exp2f(c_[nt][2] * LOG2E);
            float p3 = exp2f(c_[nt][3] * LOG2E);
            c_[nt][0] = p0; c_[nt][1] = p1; c_[nt][2] = p2; c_[nt][3] = p3;
            l0 += p0 + p1;
            l1 += p2 + p3;
        }

        uint32_t aPh[4][4], aPl[4][4];
#pragma unroll
        for (int kc = 0; kc < 4; kc++) {
            splitpack(c_[2 * kc][0],     c_[2 * kc][1],     aPh[kc][0], aPl[kc][0]);
            splitpack(c_[2 * kc][2],     c_[2 * kc][3],     aPh[kc][1], aPl[kc][1]);
            splitpack(c_[2 * kc + 1][0], c_[2 * kc + 1][1], aPh[kc][2], aPl[kc][2]);
            splitpack(c_[2 * kc + 1][2], c_[2 * kc + 1][3], aPh[kc][3], aPl[kc][3]);
        }

#pragma unroll
        for (int nt = 0; nt < 8; nt++) {
#pragma unroll
            for (int kc = 0; kc < 4; kc++) {
                const int vr = kc * 16 + (lane & 15);
                uint32_t bh0, bh1, bl0, bl1;
                ldsm_x2_trans(bh0, bh1, &sVh[vr * 72 + nt * 8]);
                ldsm_x2_trans(bl0, bl1, &sVl[vr * 72 + nt * 8]);
                mma_bf16(O[nt], aPh[kc], bh0, bh1);
                mma_bf16(O[nt], aPh[kc], bl0, bl1);
                mma_bf16(O[nt], aPl[kc], bh0, bh1);
            }
        }
        __syncthreads();
    }

    l0 += __shfl_xor_sync(0xFFFFFFFFu, l0, 1);
    l0 += __shfl_xor_sync(0xFFFFFFFFu, l0, 2);
    l1 += __shfl_xor_sync(0xFFFFFFFFu, l1, 1);
    l1 += __shfl_xor_sync(0xFFFFFFFFu, l1, 2);
    const float inv0 = 1.0f / l0, inv1 = 1.0f / l1;
#pragma unroll
    for (int nt = 0; nt < 8; nt++) {
        const int col = h * DH + nt * 8 + 2 * lm4;
        float2 o0 = make_float2(O[nt][0] * inv0, O[nt][1] * inv0);
        float2 o1 = make_float2(O[nt][2] * inv1, O[nt][3] * inv1);
        *(float2*)&g_ao[((size_t)(b * SS + qrow)) * DD + col] = o0;
        *(float2*)&g_ao[((size_t)(b * SS + qrow + 8)) * DD + col] = o1;
    }
}

// ---------------- launch ------------------------------------------------------
extern "C" void kernel_launch(void* const* d_in, const int* in_sizes, int n_in,
                              void* d_out, int out_size) {
    const float* x    = (const float*)d_in[0];
    const void*  mask = d_in[1];
    const float* bias = (const float*)d_in[2];
    const float* Wqkv = (const float*)d_in[3];
    const float* bqkv = (const float*)d_in[4];
    const float* Wout = (const float*)d_in[5];
    const float* bout = (const float*)d_in[6];
    float* out = (float*)d_out;

    float* ao = nullptr;
    cudaGetSymbolAddress((void**)&ao, g_ao);

    cudaFuncSetAttribute(flash_kernel,
                         cudaFuncAttributeMaxDynamicSharedMemorySize, FLASH_SMEM);

    detect_mask_kind_kernel<<<1, 256>>>((const unsigned int*)mask);

    // qkv GEMM with fused bias+RoPE+split epilogue (writes g_qs/g_kh/.../g_vl)
    mma_gemm_bias_kernel<<<dim3(24, 64), 128>>>(x, Wqkv, bqkv, nullptr,
                                                BB * SS, 3 * DD, DD, 1);

    // biasT + mask -> bf16
    biast3_kernel<<<dim3(SS / 512, SS, BB), 256>>>(bias, mask);

    // fused attention (3 CTAs/SM)
    flash_kernel<<<dim3(SS / 64, BB * HH), 128, FLASH_SMEM>>>();

    // out = a_out @ W_out + b_out
    mma_gemm_bias_kernel<<<dim3(8, 64), 128>>>(ao, Wout, bout, out,
                                               BB * SS, DD, DD, 0);
}

// round 16
// speedup vs baseline: 1.5607x; 1.5607x over previous
#include <cuda_runtime.h>
#include <cuda_bf16.h>
#include <math.h>
#include <stdint.h>

// Problem constants
#define BB 2
#define SS 2048
#define DD 1024
#define HH 16
#define DH 64

#define LOG2E 1.4426950408889634f

// ---------------- scratch (static device globals; no allocation) -------------
__device__ float g_qkv[BB * SS * 3 * DD];                     // 50 MB
__device__ float g_qs[BB * HH * SS * DH];                     // 16 MB
__device__ __nv_bfloat16 g_kh[BB * HH * SS * DH];             // 8 MB
__device__ __nv_bfloat16 g_kl[BB * HH * SS * DH];             // 8 MB
__device__ __nv_bfloat16 g_vh[BB * HH * SS * DH];             // 8 MB
__device__ __nv_bfloat16 g_vl[BB * HH * SS * DH];             // 8 MB
__device__ __nv_bfloat16 g_bt[(size_t)BB * HH * SS * SS];     // 268 MB
__device__ float g_ao[BB * SS * DD];                          // 16 MB
__device__ int   g_mask_kind;                                 // 0=u8, 1=i32, 2=f32

// ---------------- mask dtype detection (parallel) -----------------------------
__global__ void detect_mask_kind_kernel(const unsigned int* __restrict__ m) {
    __shared__ int f[2];
    const int t = threadIdx.x;
    if (t < 2) f[t] = 0;
    __syncthreads();
    bool sawFloat = false, sawBig = false;
#pragma unroll
    for (int j = 0; j < 4; j++) {
        unsigned int w = m[t * 4 + j];
        if (w == 0x3F800000u) sawFloat = true;
        else if (w > 1u) sawBig = true;
    }
    if (sawFloat) atomicOr(&f[0], 1);
    if (sawBig)   atomicOr(&f[1], 1);
    __syncthreads();
    if (t == 0) g_mask_kind = f[0] ? 2 : (f[1] ? 0 : 1);
}

__device__ __forceinline__ bool mask_at(const void* mask, int kind, int idx) {
    if (kind == 0) return ((const unsigned char*)mask)[idx] != 0;
    if (kind == 1) return ((const int*)mask)[idx] != 0;
    return ((const float*)mask)[idx] != 0.0f;
}

// ---------------- bf16-split helpers -----------------------------------------
__device__ __forceinline__ void split1(float x, __nv_bfloat16& h, __nv_bfloat16& l) {
    h = __float2bfloat16_rn(x);
    l = __float2bfloat16_rn(x - __bfloat162float(h));
}

__device__ __forceinline__ void splitpack(float x, float y, uint32_t& hi, uint32_t& lo) {
    __nv_bfloat16 hx, lx, hy, ly;
    split1(x, hx, lx);
    split1(y, hy, ly);
    __nv_bfloat162 H = __halves2bfloat162(hx, hy);
    __nv_bfloat162 L = __halves2bfloat162(lx, ly);
    hi = *reinterpret_cast<uint32_t*>(&H);
    lo = *reinterpret_cast<uint32_t*>(&L);
}

__device__ __forceinline__ void mma_bf16(float c[4], const uint32_t a[4],
                                         uint32_t b0, uint32_t b1) {
    asm volatile(
        "mma.sync.aligned.m16n8k16.row.col.f32.bf16.bf16.f32 "
        "{%0,%1,%2,%3}, {%4,%5,%6,%7}, {%8,%9}, {%0,%1,%2,%3};"
        : "+f"(c[0]), "+f"(c[1]), "+f"(c[2]), "+f"(c[3])
        : "r"(a[0]), "r"(a[1]), "r"(a[2]), "r"(a[3]), "r"(b0), "r"(b1));
}

__device__ __forceinline__ void ldsm_x2_trans(uint32_t& r0, uint32_t& r1, const void* p) {
    uint32_t a = (uint32_t)__cvta_generic_to_shared(p);
    asm volatile("ldmatrix.sync.aligned.m8n8.x2.trans.shared.b16 {%0,%1}, [%2];"
                 : "=r"(r0), "=r"(r1) : "r"(a));
}

__device__ __forceinline__ void ldsm_x4_trans(uint32_t& r0, uint32_t& r1, uint32_t& r2,
                                              uint32_t& r3, const void* p) {
    uint32_t a = (uint32_t)__cvta_generic_to_shared(p);
    asm volatile("ldmatrix.sync.aligned.m8n8.x4.trans.shared.b16 {%0,%1,%2,%3}, [%4];"
                 : "=r"(r0), "=r"(r1), "=r"(r2), "=r"(r3) : "r"(a));
}

__device__ __forceinline__ void ldsm_x4(uint32_t& r0, uint32_t& r1, uint32_t& r2,
                                        uint32_t& r3, const void* p) {
    uint32_t a = (uint32_t)__cvta_generic_to_shared(p);
    asm volatile("ldmatrix.sync.aligned.m8n8.x4.shared.b16 {%0,%1,%2,%3}, [%4];"
                 : "=r"(r0), "=r"(r1), "=r"(r2), "=r"(r3) : "r"(a));
}

#define CP_ASYNC16(dst_u32, src_ptr) \
    asm volatile("cp.async.ca.shared.global [%0], [%1], 16;" \
                 :: "r"(dst_u32), "l"(src_ptr))
#define CP_COMMIT() asm volatile("cp.async.commit_group;")
#define CP_WAIT(N)  asm volatile("cp.async.wait_group %0;" :: "n"(N))

// ---------------- tensor-core GEMM: C = A[M,K] @ B[K,N] + bias[N] ------------
// R8-verified config: 128 threads (4 warps, 2x2), CTA tile 64x128, BK=32,
// register-prefetch pipeline, in-loop split, 3 CTAs/SM.
__global__ __launch_bounds__(128) void mma_gemm_bias_kernel(
    const float* __restrict__ A, const float* __restrict__ B,
    const float* __restrict__ bias, float* __restrict__ C,
    int M, int N, int K)
{
    __shared__ __align__(16) __nv_bfloat16 Ah[64][40];
    __shared__ __align__(16) __nv_bfloat16 Al[64][40];
    __shared__ __align__(16) __nv_bfloat16 Bh[32][136];
    __shared__ __align__(16) __nv_bfloat16 Bl[32][136];

    const int t = threadIdx.x, w = t >> 5, lane = t & 31;
    const int wm = (w & 1) * 32, wn = (w >> 1) * 64;
    const int row0 = blockIdx.y * 64, col0 = blockIdx.x * 128;

    float acc[2][8][4];
#pragma unroll
    for (int mf = 0; mf < 2; mf++)
#pragma unroll
        for (int nf = 0; nf < 8; nf++)
#pragma unroll
            for (int r = 0; r < 4; r++) acc[mf][nf][r] = 0.f;

    const int ar = t >> 1, ac = (t & 1) * 16;
    const int br = t >> 4, bc = (t & 15) * 8;
    const float* Ag = A + (size_t)(row0 + ar) * K + ac;
    const float* Bg = B + (size_t)br * N + col0 + bc;

    float4 ra[4], rb[8];
#pragma unroll
    for (int i = 0; i < 4; i++) ra[i] = *(const float4*)(Ag + i * 4);
#pragma unroll
    for (int rr = 0; rr < 4; rr++) {
        rb[rr * 2 + 0] = *(const float4*)(Bg + (size_t)(rr * 8) * N);
        rb[rr * 2 + 1] = *(const float4*)(Bg + (size_t)(rr * 8) * N + 4);
    }

    for (int k0 = 0; k0 < K; k0 += 32) {
        {
            __nv_bfloat16 hb[16], lb[16];
            const float* f = (const float*)ra;
#pragma unroll
            for (int j = 0; j < 16; j++) split1(f[j], hb[j], lb[j]);
            *(uint4*)&Ah[ar][ac]     = *(uint4*)&hb[0];
            *(uint4*)&Ah[ar][ac + 8] = *(uint4*)&hb[8];
            *(uint4*)&Al[ar][ac]     = *(uint4*)&lb[0];
            *(uint4*)&Al[ar][ac + 8] = *(uint4*)&lb[8];
            f = (const float*)rb;
#pragma unroll
            for (int rr = 0; rr < 4; rr++) {
                __nv_bfloat16 h8[8], l8[8];
#pragma unroll
                for (int j = 0; j < 8; j++) split1(f[rr * 8 + j], h8[j], l8[j]);
                *(uint4*)&Bh[rr * 8 + br][bc] = *(uint4*)&h8[0];
                *(uint4*)&Bl[rr * 8 + br][bc] = *(uint4*)&l8[0];
            }
        }
        __syncthreads();

        if (k0 + 32 < K) {
#pragma unroll
            for (int i = 0; i < 4; i++)
                ra[i] = *(const float4*)(Ag + (k0 + 32) + i * 4);
#pragma unroll
            for (int rr = 0; rr < 4; rr++) {
                rb[rr * 2 + 0] = *(const float4*)(Bg + (size_t)(k0 + 32 + rr * 8) * N);
                rb[rr * 2 + 1] = *(const float4*)(Bg + (size_t)(k0 + 32 + rr * 8) * N + 4);
            }
        }

#pragma unroll
        for (int ks = 0; ks < 2; ks++) {
            const int kk = ks * 16;
            uint32_t a_h[2][4], a_l[2][4];
#pragma unroll
            for (int mf = 0; mf < 2; mf++) {
                const int r = wm + mf * 16 + (lane & 15);
                const int c = kk + (lane >> 4) * 8;
                ldsm_x4(a_h[mf][0], a_h[mf][1], a_h[mf][2], a_h[mf][3], &Ah[r][c]);
                ldsm_x4(a_l[mf][0], a_l[mf][1], a_l[mf][2], a_l[mf][3], &Al[r][c]);
            }
#pragma unroll
            for (int nf = 0; nf < 8; nf++) {
                const int krow = kk + (lane & 15);
                const int nc = wn + nf * 8;
                uint32_t bh0, bh1, bl0, bl1;
                ldsm_x2_trans(bh0, bh1, &Bh[krow][nc]);
                ldsm_x2_trans(bl0, bl1, &Bl[krow][nc]);
#pragma unroll
                for (int mf = 0; mf < 2; mf++) {
                    mma_bf16(acc[mf][nf], a_h[mf], bh0, bh1);
                    mma_bf16(acc[mf][nf], a_h[mf], bl0, bl1);
                    mma_bf16(acc[mf][nf], a_l[mf], bh0, bh1);
                }
            }
        }
        __syncthreads();
    }

#pragma unroll
    for (int mf = 0; mf < 2; mf++) {
#pragma unroll
        for (int nf = 0; nf < 8; nf++) {
            const int r = row0 + wm + mf * 16 + (lane >> 2);
            const int c = col0 + wn + nf * 8 + (lane & 3) * 2;
            const float bx = bias[c], by = bias[c + 1];
            float2 o0 = make_float2(acc[mf][nf][0] + bx, acc[mf][nf][1] + by);
            float2 o1 = make_float2(acc[mf][nf][2] + bx, acc[mf][nf][3] + by);
            *(float2*)&C[(size_t)r * N + c] = o0;
            *(float2*)&C[(size_t)(r + 8) * N + c] = o1;
        }
    }
}

// ---------------- RoPE + head split + hi/lo presplit -------------------------
__global__ __launch_bounds__(256) void rope_split_kernel() {
    const int i = blockIdx.x * 256 + threadIdx.x;
    const int j = i & 31;
    const int h = (i >> 5) & 15;
    const int s = (i >> 9) & 2047;
    const int b = i >> 20;
    const float* base = g_qkv + ((size_t)(b * SS + s)) * (3 * DD) + h * DH;

    const float ex = (float)(2 * j) / 64.0f;
    const float scale = 1.0f / powf(10000.0f, ex);
    const float ang = (float)s * scale;
    const float c = cosf(ang), sn = sinf(ang);

    const size_t ob = (((size_t)(b * HH + h)) * SS + s) * DH;
    float q1 = base[j], q2 = base[j + 32];
    g_qs[ob + j]      = q1 * c - q2 * sn;
    g_qs[ob + j + 32] = q2 * c + q1 * sn;

    __nv_bfloat16 hh, ll;
    float k1 = base[DD + j], k2 = base[DD + j + 32];
    split1(k1 * c - k2 * sn, hh, ll);
    g_kh[ob + j] = hh;      g_kl[ob + j] = ll;
    split1(k2 * c + k1 * sn, hh, ll);
    g_kh[ob + j + 32] = hh; g_kl[ob + j + 32] = ll;

    split1(base[2 * DD + j], hh, ll);
    g_vh[ob + j] = hh;      g_vl[ob + j] = ll;
    split1(base[2 * DD + j + 32], hh, ll);
    g_vh[ob + j + 32] = hh; g_vl[ob + j + 32] = ll;
}

// ---------------- bias transpose + mask -> bf16 (no smem) --------------------
__global__ __launch_bounds__(256) void biast3_kernel(
    const float* __restrict__ bias, const void* __restrict__ mask)
{
    const int b = blockIdx.z, q = blockIdx.y;
    const int k0 = (blockIdx.x * 256 + threadIdx.x) * 2;
    const float* src = bias + (((size_t)(b * SS + q)) * SS + k0) * HH;
    const int kind = g_mask_kind;
    const bool m0 = mask_at(mask, kind, b * SS + k0);
    const bool m1 = mask_at(mask, kind, b * SS + k0 + 1);

    float f[32];
#pragma unroll
    for (int i = 0; i < 8; i++) *(float4*)&f[i * 4] = ((const float4*)src)[i];

    const __nv_bfloat16 NINF = __float2bfloat16(-INFINITY);
    const size_t outbase = ((size_t)b * HH * SS + q) * SS + k0;
#pragma unroll
    for (int h = 0; h < HH; h++) {
        __nv_bfloat162 pk;
        pk.x = m0 ? __float2bfloat16(f[h]) : NINF;
        pk.y = m1 ? __float2bfloat16(f[16 + h]) : NINF;
        *(__nv_bfloat162*)&g_bt[outbase + (size_t)h * SS * SS] = pk;
    }
}

// ---------------- fused flash attention --------------------------------------
// 128 threads (4 warps), q-tile 64, 2 CTAs/SM (natural regs), cp.async
// double-buffered, K frags via ldmatrix.x4, fixed-base softmax.
// NEW: V frags via ldmatrix.x4.trans serving two nt-columns per instruction
// (halves PV LDSM issue count; identical operands & MMA order).
#define TILE_BUF 9216
#define OFF_KH 0
#define OFF_KL 18432
#define OFF_VH 36864
#define OFF_VL 55296
#define FLASH_SMEM 73728

__global__ __launch_bounds__(128) void flash_kernel() {
    extern __shared__ __align__(16) char sm[];
    const uint32_t smem_base = (uint32_t)__cvta_generic_to_shared(sm);

    const int bh = blockIdx.y;
    const int b = bh >> 4, h = bh & 15;
    const int q0 = blockIdx.x * 64;
    const int t = threadIdx.x;
    const int w = t >> 5, lane = t & 31;
    const int l4 = lane >> 2, lm4 = lane & 3;

    const float* Qg = g_qs + (size_t)bh * SS * DH;
    const __nv_bfloat16* Khg = g_kh + (size_t)bh * SS * DH;
    const __nv_bfloat16* Klg = g_kl + (size_t)bh * SS * DH;
    const __nv_bfloat16* Vhg = g_vh + (size_t)bh * SS * DH;
    const __nv_bfloat16* Vlg = g_vl + (size_t)bh * SS * DH;
    const __nv_bfloat16* Bt = g_bt + (size_t)bh * SS * SS;

    const int qrow = q0 + w * 16 + l4;

    const int cr0 = t >> 3, cc = (t & 7) * 8;

#define COPY_TILE(kt, buf)                                                          \
    {                                                                               \
        const int kb = (kt) * 64;                                                   \
        _Pragma("unroll")                                                           \
        for (int ii = 0; ii < 4; ii++) {                                            \
            const int r = cr0 + ii * 16;                                            \
            const uint32_t d = smem_base + (buf) * TILE_BUF + r * 144 + cc * 2;     \
            CP_ASYNC16(d + OFF_KH, Khg + (size_t)(kb + r) * DH + cc);               \
            CP_ASYNC16(d + OFF_KL, Klg + (size_t)(kb + r) * DH + cc);               \
            CP_ASYNC16(d + OFF_VH, Vhg + (size_t)(kb + r) * DH + cc);               \
            CP_ASYNC16(d + OFF_VL, Vlg + (size_t)(kb + r) * DH + cc);               \
        }                                                                           \
        CP_COMMIT();                                                                \
    }

    uint32_t aQh[4][4], aQl[4][4];
#pragma unroll
    for (int kc = 0; kc < 4; kc++) {
        const int c0 = kc * 16 + 2 * lm4;
        float2 x0 = *(const float2*)&Qg[(size_t)qrow * DH + c0];
        float2 x1 = *(const float2*)&Qg[(size_t)(qrow + 8) * DH + c0];
        float2 x2 = *(const float2*)&Qg[(size_t)qrow * DH + c0 + 8];
        float2 x3 = *(const float2*)&Qg[(size_t)(qrow + 8) * DH + c0 + 8];
        splitpack(x0.x * 0.125f, x0.y * 0.125f, aQh[kc][0], aQl[kc][0]);
        splitpack(x1.x * 0.125f, x1.y * 0.125f, aQh[kc][1], aQl[kc][1]);
        splitpack(x2.x * 0.125f, x2.y * 0.125f, aQh[kc][2], aQl[kc][2]);
        splitpack(x3.x * 0.125f, x3.y * 0.125f, aQh[kc][3], aQl[kc][3]);
    }

    COPY_TILE(0, 0);

    float l0 = 0.f, l1 = 0.f;
    float O[8][4];
#pragma unroll
    for (int nt = 0; nt < 8; nt++)
#pragma unroll
        for (int j = 0; j < 4; j++) O[nt][j] = 0.f;

    for (int kt = 0; kt < SS / 64; kt++) {
        const int buf = kt & 1;
        const int k0 = kt * 64;
        if (kt + 1 < SS / 64) {
            COPY_TILE(kt + 1, buf ^ 1);
            CP_WAIT(1);
        } else {
            CP_WAIT(0);
        }
        __syncthreads();

        const __nv_bfloat16* sKh = (const __nv_bfloat16*)(sm + OFF_KH) + buf * 4608;
        const __nv_bfloat16* sKl = (const __nv_bfloat16*)(sm + OFF_KL) + buf * 4608;
        const __nv_bfloat16* sVh = (const __nv_bfloat16*)(sm + OFF_VH) + buf * 4608;
        const __nv_bfloat16* sVl = (const __nv_bfloat16*)(sm + OFF_VL) + buf * 4608;
        const __nv_bfloat16* Btp = Bt + (size_t)qrow * SS + k0;

        // ---- S = bias; S += (Q/8) @ K^T; K frags via ldmatrix.x4 ----
        float c_[8][4];
#pragma unroll
        for (int nt = 0; nt < 8; nt++) {
            const int kcc = nt * 8 + 2 * lm4;
            __nv_bfloat162 b01 = *(const __nv_bfloat162*)&Btp[kcc];
            __nv_bfloat162 b23 = *(const __nv_bfloat162*)&Btp[8 * SS + kcc];
            c_[nt][0] = __bfloat162float(b01.x); c_[nt][1] = __bfloat162float(b01.y);
            c_[nt][2] = __bfloat162float(b23.x); c_[nt][3] = __bfloat162float(b23.y);
        }
#pragma unroll
        for (int nt = 0; nt < 8; nt++) {
            const int krow = nt * 8 + (lane & 7);
            const int csel = (lane >> 3) * 8;
            uint32_t kh[8], kl[8];
            ldsm_x4(kh[0], kh[1], kh[2], kh[3], &sKh[krow * 72 + csel]);
            ldsm_x4(kh[4], kh[5], kh[6], kh[7], &sKh[krow * 72 + 32 + csel]);
            ldsm_x4(kl[0], kl[1], kl[2], kl[3], &sKl[krow * 72 + csel]);
            ldsm_x4(kl[4], kl[5], kl[6], kl[7], &sKl[krow * 72 + 32 + csel]);
#pragma unroll
            for (int kc = 0; kc < 4; kc++) {
                mma_bf16(c_[nt], aQh[kc], kh[2 * kc], kh[2 * kc + 1]);
                mma_bf16(c_[nt], aQh[kc], kl[2 * kc], kl[2 * kc + 1]);
                mma_bf16(c_[nt], aQl[kc], kh[2 * kc], kh[2 * kc + 1]);
            }
        }

        // ---- fixed-base softmax ----
#pragma unroll
        for (int nt = 0; nt < 8; nt++) {
            float p0 = exp2f(c_[nt][0] * LOG2E);
            float p1 = exp2f(c_[nt][1] * LOG2E);
            float p2 = exp2f(c_[nt][2] * LOG2E);
            float p3 = exp2f(c_[nt][3] * LOG2E);
            c_[nt][0] = p0; c_[nt][1] = p1; c_[nt][2] = p2; c_[nt][3] = p3;
            l0 += p0 + p1;
            l1 += p2 + p3;
        }

        // ---- P fragments (bf16 hi/lo) ----
        uint32_t aPh[4][4], aPl[4][4];
#pragma unroll
        for (int kc = 0; kc < 4; kc++) {
            splitpack(c_[2 * kc][0],     c_[2 * kc][1],     aPh[kc][0], aPl[kc][0]);
            splitpack(c_[2 * kc][2],     c_[2 * kc][3],     aPh[kc][1], aPl[kc][1]);
            splitpack(c_[2 * kc + 1][0], c_[2 * kc + 1][1], aPh[kc][2], aPl[kc][2]);
            splitpack(c_[2 * kc + 1][2], c_[2 * kc + 1][3], aPh[kc][3], aPl[kc][3]);
        }

        // ---- O += P @ V; V frags via ldmatrix.x4.trans (2 nt per instr) ----
#pragma unroll
        for (int nt = 0; nt < 8; nt += 2) {
#pragma unroll
            for (int kc = 0; kc < 4; kc++) {
                const int vr = kc * 16 + (lane & 15);
                const int nn = (nt + (lane >> 4)) * 8;
                uint32_t h0, h1, h2, h3, v0, v1, v2, v3;
                ldsm_x4_trans(h0, h1, h2, h3, &sVh[vr * 72 + nn]);
                ldsm_x4_trans(v0, v1, v2, v3, &sVl[vr * 72 + nn]);
                mma_bf16(O[nt], aPh[kc], h0, h1);
                mma_bf16(O[nt], aPh[kc], v0, v1);
                mma_bf16(O[nt], aPl[kc], h0, h1);
                mma_bf16(O[nt + 1], aPh[kc], h2, h3);
                mma_bf16(O[nt + 1], aPh[kc], v2, v3);
                mma_bf16(O[nt + 1], aPl[kc], h2, h3);
            }
        }
        __syncthreads();
    }

    l0 += __shfl_xor_sync(0xFFFFFFFFu, l0, 1);
    l0 += __shfl_xor_sync(0xFFFFFFFFu, l0, 2);
    l1 += __shfl_xor_sync(0xFFFFFFFFu, l1, 1);
    l1 += __shfl_xor_sync(0xFFFFFFFFu, l1, 2);
    const float inv0 = 1.0f / l0, inv1 = 1.0f / l1;
#pragma unroll
    for (int nt = 0; nt < 8; nt++) {
        const int col = h * DH + nt * 8 + 2 * lm4;
        float2 o0 = make_float2(O[nt][0] * inv0, O[nt][1] * inv0);
        float2 o1 = make_float2(O[nt][2] * inv1, O[nt][3] * inv1);
        *(float2*)&g_ao[((size_t)(b * SS + qrow)) * DD + col] = o0;
        *(float2*)&g_ao[((size_t)(b * SS + qrow + 8)) * DD + col] = o1;
    }
}

// ---------------- launch ------------------------------------------------------
extern "C" void kernel_launch(void* const* d_in, const int* in_sizes, int n_in,
                              void* d_out, int out_size) {
    const float* x    = (const float*)d_in[0];
    const void*  mask = d_in[1];
    const float* bias = (const float*)d_in[2];
    const float* Wqkv = (const float*)d_in[3];
    const float* bqkv = (const float*)d_in[4];
    const float* Wout = (const float*)d_in[5];
    const float* bout = (const float*)d_in[6];
    float* out = (float*)d_out;

    float *qkv = nullptr, *ao = nullptr;
    cudaGetSymbolAddress((void**)&qkv, g_qkv);
    cudaGetSymbolAddress((void**)&ao, g_ao);

    cudaFuncSetAttribute(flash_kernel,
                         cudaFuncAttributeMaxDynamicSharedMemorySize, FLASH_SMEM);

    detect_mask_kind_kernel<<<1, 256>>>((const unsigned int*)mask);

    // qkv = x @ W_qkv + b_qkv
    mma_gemm_bias_kernel<<<dim3(24, 64), 128>>>(x, Wqkv, bqkv, qkv, BB * SS, 3 * DD, DD);

    // head split + RoPE + hi/lo presplit of K,V
    rope_split_kernel<<<(BB * SS * HH * 32) / 256, 256>>>();

    // biasT + mask -> bf16
    biast3_kernel<<<dim3(SS / 512, SS, BB), 256>>>(bias, mask);

    // fused attention
    flash_kernel<<<dim3(SS / 64, BB * HH), 128, FLASH_SMEM>>>();

    // out = a_out @ W_out + b_out
    mma_gemm_bias_kernel<<<dim3(8, 64), 128>>>(ao, Wout, bout, out, BB * SS, DD, DD);
}

// round 17
// speedup vs baseline: 1.5828x; 1.0142x over previous
#include <cuda_runtime.h>
#include <cuda_bf16.h>
#include <math.h>
#include <stdint.h>

// Problem constants
#define BB 2
#define SS 2048
#define DD 1024
#define HH 16
#define DH 64

#define LOG2E 1.4426950408889634f

// ---------------- scratch (static device globals; no allocation) -------------
__device__ float g_qkv[BB * SS * 3 * DD];                     // 50 MB
__device__ float g_qs[BB * HH * SS * DH];                     // 16 MB
__device__ __nv_bfloat16 g_kh[BB * HH * SS * DH];             // 8 MB
__device__ __nv_bfloat16 g_kl[BB * HH * SS * DH];             // 8 MB
__device__ __nv_bfloat16 g_vh[BB * HH * SS * DH];             // 8 MB
__device__ __nv_bfloat16 g_vl[BB * HH * SS * DH];             // 8 MB
__device__ __nv_bfloat16 g_bt[(size_t)BB * HH * SS * SS];     // 268 MB
__device__ float g_ao[BB * SS * DD];                          // 16 MB
__device__ int   g_mask_kind;                                 // 0=u8, 1=i32, 2=f32

// ---------------- mask dtype detection (parallel) -----------------------------
__global__ void detect_mask_kind_kernel(const unsigned int* __restrict__ m) {
    __shared__ int f[2];
    const int t = threadIdx.x;
    if (t < 2) f[t] = 0;
    __syncthreads();
    bool sawFloat = false, sawBig = false;
#pragma unroll
    for (int j = 0; j < 4; j++) {
        unsigned int w = m[t * 4 + j];
        if (w == 0x3F800000u) sawFloat = true;
        else if (w > 1u) sawBig = true;
    }
    if (sawFloat) atomicOr(&f[0], 1);
    if (sawBig)   atomicOr(&f[1], 1);
    __syncthreads();
    if (t == 0) g_mask_kind = f[0] ? 2 : (f[1] ? 0 : 1);
}

__device__ __forceinline__ bool mask_at(const void* mask, int kind, int idx) {
    if (kind == 0) return ((const unsigned char*)mask)[idx] != 0;
    if (kind == 1) return ((const int*)mask)[idx] != 0;
    return ((const float*)mask)[idx] != 0.0f;
}

// ---------------- bf16-split helpers -----------------------------------------
__device__ __forceinline__ void split1(float x, __nv_bfloat16& h, __nv_bfloat16& l) {
    h = __float2bfloat16_rn(x);
    l = __float2bfloat16_rn(x - __bfloat162float(h));
}

__device__ __forceinline__ void splitpack(float x, float y, uint32_t& hi, uint32_t& lo) {
    __nv_bfloat16 hx, lx, hy, ly;
    split1(x, hx, lx);
    split1(y, hy, ly);
    __nv_bfloat162 H = __halves2bfloat162(hx, hy);
    __nv_bfloat162 L = __halves2bfloat162(lx, ly);
    hi = *reinterpret_cast<uint32_t*>(&H);
    lo = *reinterpret_cast<uint32_t*>(&L);
}

__device__ __forceinline__ void mma_bf16(float c[4], const uint32_t a[4],
                                         uint32_t b0, uint32_t b1) {
    asm volatile(
        "mma.sync.aligned.m16n8k16.row.col.f32.bf16.bf16.f32 "
        "{%0,%1,%2,%3}, {%4,%5,%6,%7}, {%8,%9}, {%0,%1,%2,%3};"
        : "+f"(c[0]), "+f"(c[1]), "+f"(c[2]), "+f"(c[3])
        : "r"(a[0]), "r"(a[1]), "r"(a[2]), "r"(a[3]), "r"(b0), "r"(b1));
}

__device__ __forceinline__ void ldsm_x4_trans(uint32_t& r0, uint32_t& r1, uint32_t& r2,
                                              uint32_t& r3, const void* p) {
    uint32_t a = (uint32_t)__cvta_generic_to_shared(p);
    asm volatile("ldmatrix.sync.aligned.m8n8.x4.trans.shared.b16 {%0,%1,%2,%3}, [%4];"
                 : "=r"(r0), "=r"(r1), "=r"(r2), "=r"(r3) : "r"(a));
}

__device__ __forceinline__ void ldsm_x4(uint32_t& r0, uint32_t& r1, uint32_t& r2,
                                        uint32_t& r3, const void* p) {
    uint32_t a = (uint32_t)__cvta_generic_to_shared(p);
    asm volatile("ldmatrix.sync.aligned.m8n8.x4.shared.b16 {%0,%1,%2,%3}, [%4];"
                 : "=r"(r0), "=r"(r1), "=r"(r2), "=r"(r3) : "r"(a));
}

#define CP_ASYNC16(dst_u32, src_ptr) \
    asm volatile("cp.async.ca.shared.global [%0], [%1], 16;" \
                 :: "r"(dst_u32), "l"(src_ptr))
#define CP_COMMIT() asm volatile("cp.async.commit_group;")
#define CP_WAIT(N)  asm volatile("cp.async.wait_group %0;" :: "n"(N))

// ---------------- tensor-core GEMM: C = A[M,K] @ B[K,N] + bias[N] ------------
// R8-verified config: 128 threads (4 warps, 2x2), CTA tile 64x128, BK=32,
// register-prefetch pipeline, in-loop split, 3 CTAs/SM.
// NEW: B fragments via ldmatrix.x4.trans serving two nf per instruction.
__global__ __launch_bounds__(128) void mma_gemm_bias_kernel(
    const float* __restrict__ A, const float* __restrict__ B,
    const float* __restrict__ bias, float* __restrict__ C,
    int M, int N, int K)
{
    __shared__ __align__(16) __nv_bfloat16 Ah[64][40];
    __shared__ __align__(16) __nv_bfloat16 Al[64][40];
    __shared__ __align__(16) __nv_bfloat16 Bh[32][136];
    __shared__ __align__(16) __nv_bfloat16 Bl[32][136];

    const int t = threadIdx.x, w = t >> 5, lane = t & 31;
    const int wm = (w & 1) * 32, wn = (w >> 1) * 64;
    const int row0 = blockIdx.y * 64, col0 = blockIdx.x * 128;

    float acc[2][8][4];
#pragma unroll
    for (int mf = 0; mf < 2; mf++)
#pragma unroll
        for (int nf = 0; nf < 8; nf++)
#pragma unroll
            for (int r = 0; r < 4; r++) acc[mf][nf][r] = 0.f;

    const int ar = t >> 1, ac = (t & 1) * 16;
    const int br = t >> 4, bc = (t & 15) * 8;
    const float* Ag = A + (size_t)(row0 + ar) * K + ac;
    const float* Bg = B + (size_t)br * N + col0 + bc;

    float4 ra[4], rb[8];
#pragma unroll
    for (int i = 0; i < 4; i++) ra[i] = *(const float4*)(Ag + i * 4);
#pragma unroll
    for (int rr = 0; rr < 4; rr++) {
        rb[rr * 2 + 0] = *(const float4*)(Bg + (size_t)(rr * 8) * N);
        rb[rr * 2 + 1] = *(const float4*)(Bg + (size_t)(rr * 8) * N + 4);
    }

    for (int k0 = 0; k0 < K; k0 += 32) {
        {
            __nv_bfloat16 hb[16], lb[16];
            const float* f = (const float*)ra;
#pragma unroll
            for (int j = 0; j < 16; j++) split1(f[j], hb[j], lb[j]);
            *(uint4*)&Ah[ar][ac]     = *(uint4*)&hb[0];
            *(uint4*)&Ah[ar][ac + 8] = *(uint4*)&hb[8];
            *(uint4*)&Al[ar][ac]     = *(uint4*)&lb[0];
            *(uint4*)&Al[ar][ac + 8] = *(uint4*)&lb[8];
            f = (const float*)rb;
#pragma unroll
            for (int rr = 0; rr < 4; rr++) {
                __nv_bfloat16 h8[8], l8[8];
#pragma unroll
                for (int j = 0; j < 8; j++) split1(f[rr * 8 + j], h8[j], l8[j]);
                *(uint4*)&Bh[rr * 8 + br][bc] = *(uint4*)&h8[0];
                *(uint4*)&Bl[rr * 8 + br][bc] = *(uint4*)&l8[0];
            }
        }
        __syncthreads();

        if (k0 + 32 < K) {
#pragma unroll
            for (int i = 0; i < 4; i++)
                ra[i] = *(const float4*)(Ag + (k0 + 32) + i * 4);
#pragma unroll
            for (int rr = 0; rr < 4; rr++) {
                rb[rr * 2 + 0] = *(const float4*)(Bg + (size_t)(k0 + 32 + rr * 8) * N);
                rb[rr * 2 + 1] = *(const float4*)(Bg + (size_t)(k0 + 32 + rr * 8) * N + 4);
            }
        }

#pragma unroll
        for (int ks = 0; ks < 2; ks++) {
            const int kk = ks * 16;
            uint32_t a_h[2][4], a_l[2][4];
#pragma unroll
            for (int mf = 0; mf < 2; mf++) {
                const int r = wm + mf * 16 + (lane & 15);
                const int c = kk + (lane >> 4) * 8;
                ldsm_x4(a_h[mf][0], a_h[mf][1], a_h[mf][2], a_h[mf][3], &Ah[r][c]);
                ldsm_x4(a_l[mf][0], a_l[mf][1], a_l[mf][2], a_l[mf][3], &Al[r][c]);
            }
#pragma unroll
            for (int nfp = 0; nfp < 4; nfp++) {
                const int krow = kk + (lane & 15);
                const int nc = wn + (nfp * 2 + (lane >> 4)) * 8;
                uint32_t bh0, bh1, bh2, bh3, bl0, bl1, bl2, bl3;
                ldsm_x4_trans(bh0, bh1, bh2, bh3, &Bh[krow][nc]);
                ldsm_x4_trans(bl0, bl1, bl2, bl3, &Bl[krow][nc]);
#pragma unroll
                for (int mf = 0; mf < 2; mf++) {
                    mma_bf16(acc[mf][nfp * 2], a_h[mf], bh0, bh1);
                    mma_bf16(acc[mf][nfp * 2], a_h[mf], bl0, bl1);
                    mma_bf16(acc[mf][nfp * 2], a_l[mf], bh0, bh1);
                    mma_bf16(acc[mf][nfp * 2 + 1], a_h[mf], bh2, bh3);
                    mma_bf16(acc[mf][nfp * 2 + 1], a_h[mf], bl2, bl3);
                    mma_bf16(acc[mf][nfp * 2 + 1], a_l[mf], bh2, bh3);
                }
            }
        }
        __syncthreads();
    }

#pragma unroll
    for (int mf = 0; mf < 2; mf++) {
#pragma unroll
        for (int nf = 0; nf < 8; nf++) {
            const int r = row0 + wm + mf * 16 + (lane >> 2);
            const int c = col0 + wn + nf * 8 + (lane & 3) * 2;
            const float bx = bias[c], by = bias[c + 1];
            float2 o0 = make_float2(acc[mf][nf][0] + bx, acc[mf][nf][1] + by);
            float2 o1 = make_float2(acc[mf][nf][2] + bx, acc[mf][nf][3] + by);
            *(float2*)&C[(size_t)r * N + c] = o0;
            *(float2*)&C[(size_t)(r + 8) * N + c] = o1;
        }
    }
}

// ---------------- RoPE + head split + hi/lo presplit -------------------------
__global__ __launch_bounds__(256) void rope_split_kernel() {
    const int i = blockIdx.x * 256 + threadIdx.x;
    const int j = i & 31;
    const int h = (i >> 5) & 15;
    const int s = (i >> 9) & 2047;
    const int b = i >> 20;
    const float* base = g_qkv + ((size_t)(b * SS + s)) * (3 * DD) + h * DH;

    const float ex = (float)(2 * j) / 64.0f;
    const float scale = 1.0f / powf(10000.0f, ex);
    const float ang = (float)s * scale;
    const float c = cosf(ang), sn = sinf(ang);

    const size_t ob = (((size_t)(b * HH + h)) * SS + s) * DH;
    float q1 = base[j], q2 = base[j + 32];
    g_qs[ob + j]      = q1 * c - q2 * sn;
    g_qs[ob + j + 32] = q2 * c + q1 * sn;

    __nv_bfloat16 hh, ll;
    float k1 = base[DD + j], k2 = base[DD + j + 32];
    split1(k1 * c - k2 * sn, hh, ll);
    g_kh[ob + j] = hh;      g_kl[ob + j] = ll;
    split1(k2 * c + k1 * sn, hh, ll);
    g_kh[ob + j + 32] = hh; g_kl[ob + j + 32] = ll;

    split1(base[2 * DD + j], hh, ll);
    g_vh[ob + j] = hh;      g_vl[ob + j] = ll;
    split1(base[2 * DD + j + 32], hh, ll);
    g_vh[ob + j + 32] = hh; g_vl[ob + j + 32] = ll;
}

// ---------------- bias transpose + mask -> bf16 (no smem) --------------------
__global__ __launch_bounds__(256) void biast3_kernel(
    const float* __restrict__ bias, const void* __restrict__ mask)
{
    const int b = blockIdx.z, q = blockIdx.y;
    const int k0 = (blockIdx.x * 256 + threadIdx.x) * 2;
    const float* src = bias + (((size_t)(b * SS + q)) * SS + k0) * HH;
    const int kind = g_mask_kind;
    const bool m0 = mask_at(mask, kind, b * SS + k0);
    const bool m1 = mask_at(mask, kind, b * SS + k0 + 1);

    float f[32];
#pragma unroll
    for (int i = 0; i < 8; i++) *(float4*)&f[i * 4] = ((const float4*)src)[i];

    const __nv_bfloat16 NINF = __float2bfloat16(-INFINITY);
    const size_t outbase = ((size_t)b * HH * SS + q) * SS + k0;
#pragma unroll
    for (int h = 0; h < HH; h++) {
        __nv_bfloat162 pk;
        pk.x = m0 ? __float2bfloat16(f[h]) : NINF;
        pk.y = m1 ? __float2bfloat16(f[16 + h]) : NINF;
        *(__nv_bfloat162*)&g_bt[outbase + (size_t)h * SS * SS] = pk;
    }
}

// ---------------- fused flash attention --------------------------------------
// 128 threads (4 warps), q-tile 64, 2 CTAs/SM, cp.async double-buffered,
// K frags via ldmatrix.x4, V frags via ldmatrix.x4.trans (2 nt per instr),
// fixed-base softmax.
#define TILE_BUF 9216
#define OFF_KH 0
#define OFF_KL 18432
#define OFF_VH 36864
#define OFF_VL 55296
#define FLASH_SMEM 73728

__global__ __launch_bounds__(128) void flash_kernel() {
    extern __shared__ __align__(16) char sm[];
    const uint32_t smem_base = (uint32_t)__cvta_generic_to_shared(sm);

    const int bh = blockIdx.y;
    const int b = bh >> 4, h = bh & 15;
    const int q0 = blockIdx.x * 64;
    const int t = threadIdx.x;
    const int w = t >> 5, lane = t & 31;
    const int l4 = lane >> 2, lm4 = lane & 3;

    const float* Qg = g_qs + (size_t)bh * SS * DH;
    const __nv_bfloat16* Khg = g_kh + (size_t)bh * SS * DH;
    const __nv_bfloat16* Klg = g_kl + (size_t)bh * SS * DH;
    const __nv_bfloat16* Vhg = g_vh + (size_t)bh * SS * DH;
    const __nv_bfloat16* Vlg = g_vl + (size_t)bh * SS * DH;
    const __nv_bfloat16* Bt = g_bt + (size_t)bh * SS * SS;

    const int qrow = q0 + w * 16 + l4;

    const int cr0 = t >> 3, cc = (t & 7) * 8;

#define COPY_TILE(kt, buf)                                                          \
    {                                                                               \
        const int kb = (kt) * 64;                                                   \
        _Pragma("unroll")                                                           \
        for (int ii = 0; ii < 4; ii++) {                                            \
            const int r = cr0 + ii * 16;                                            \
            const uint32_t d = smem_base + (buf) * TILE_BUF + r * 144 + cc * 2;     \
            CP_ASYNC16(d + OFF_KH, Khg + (size_t)(kb + r) * DH + cc);               \
            CP_ASYNC16(d + OFF_KL, Klg + (size_t)(kb + r) * DH + cc);               \
            CP_ASYNC16(d + OFF_VH, Vhg + (size_t)(kb + r) * DH + cc);               \
            CP_ASYNC16(d + OFF_VL, Vlg + (size_t)(kb + r) * DH + cc);               \
        }                                                                           \
        CP_COMMIT();                                                                \
    }

    uint32_t aQh[4][4], aQl[4][4];
#pragma unroll
    for (int kc = 0; kc < 4; kc++) {
        const int c0 = kc * 16 + 2 * lm4;
        float2 x0 = *(const float2*)&Qg[(size_t)qrow * DH + c0];
        float2 x1 = *(const float2*)&Qg[(size_t)(qrow + 8) * DH + c0];
        float2 x2 = *(const float2*)&Qg[(size_t)qrow * DH + c0 + 8];
        float2 x3 = *(const float2*)&Qg[(size_t)(qrow + 8) * DH + c0 + 8];
        splitpack(x0.x * 0.125f, x0.y * 0.125f, aQh[kc][0], aQl[kc][0]);
        splitpack(x1.x * 0.125f, x1.y * 0.125f, aQh[kc][1], aQl[kc][1]);
        splitpack(x2.x * 0.125f, x2.y * 0.125f, aQh[kc][2], aQl[kc][2]);
        splitpack(x3.x * 0.125f, x3.y * 0.125f, aQh[kc][3], aQl[kc][3]);
    }

    COPY_TILE(0, 0);

    float l0 = 0.f, l1 = 0.f;
    float O[8][4];
#pragma unroll
    for (int nt = 0; nt < 8; nt++)
#pragma unroll
        for (int j = 0; j < 4; j++) O[nt][j] = 0.f;

    for (int kt = 0; kt < SS / 64; kt++) {
        const int buf = kt & 1;
        const int k0 = kt * 64;
        if (kt + 1 < SS / 64) {
            COPY_TILE(kt + 1, buf ^ 1);
            CP_WAIT(1);
        } else {
            CP_WAIT(0);
        }
        __syncthreads();

        const __nv_bfloat16* sKh = (const __nv_bfloat16*)(sm + OFF_KH) + buf * 4608;
        const __nv_bfloat16* sKl = (const __nv_bfloat16*)(sm + OFF_KL) + buf * 4608;
        const __nv_bfloat16* sVh = (const __nv_bfloat16*)(sm + OFF_VH) + buf * 4608;
        const __nv_bfloat16* sVl = (const __nv_bfloat16*)(sm + OFF_VL) + buf * 4608;
        const __nv_bfloat16* Btp = Bt + (size_t)qrow * SS + k0;

        float c_[8][4];
#pragma unroll
        for (int nt = 0; nt < 8; nt++) {
            const int kcc = nt * 8 + 2 * lm4;
            __nv_bfloat162 b01 = *(const __nv_bfloat162*)&Btp[kcc];
            __nv_bfloat162 b23 = *(const __nv_bfloat162*)&Btp[8 * SS + kcc];
            c_[nt][0] = __bfloat162float(b01.x); c_[nt][1] = __bfloat162float(b01.y);
            c_[nt][2] = __bfloat162float(b23.x); c_[nt][3] = __bfloat162float(b23.y);
        }
#pragma unroll
        for (int nt = 0; nt < 8; nt++) {
            const int krow = nt * 8 + (lane & 7);
            const int csel = (lane >> 3) * 8;
            uint32_t kh[8], kl[8];
            ldsm_x4(kh[0], kh[1], kh[2], kh[3], &sKh[krow * 72 + csel]);
            ldsm_x4(kh[4], kh[5], kh[6], kh[7], &sKh[krow * 72 + 32 + csel]);
            ldsm_x4(kl[0], kl[1], kl[2], kl[3], &sKl[krow * 72 + csel]);
            ldsm_x4(kl[4], kl[5], kl[6], kl[7], &sKl[krow * 72 + 32 + csel]);
#pragma unroll
            for (int kc = 0; kc < 4; kc++) {
                mma_bf16(c_[nt], aQh[kc], kh[2 * kc], kh[2 * kc + 1]);
                mma_bf16(c_[nt], aQh[kc], kl[2 * kc], kl[2 * kc + 1]);
                mma_bf16(c_[nt], aQl[kc], kh[2 * kc], kh[2 * kc + 1]);
            }
        }

#pragma unroll
        for (int nt = 0; nt < 8; nt++) {
            float p0 = exp2f(c_[nt][0] * LOG2E);
            float p1 = exp2f(c_[nt][1] * LOG2E);
            float p2 = exp2f(c_[nt][2] * LOG2E);
            float p3 = exp2f(c_[nt][3] * LOG2E);
            c_[nt][0] = p0; c_[nt][1] = p1; c_[nt][2] = p2; c_[nt][3] = p3;
            l0 += p0 + p1;
            l1 += p2 + p3;
        }

        uint32_t aPh[4][4], aPl[4][4];
#pragma unroll
        for (int kc = 0; kc < 4; kc++) {
            splitpack(c_[2 * kc][0],     c_[2 * kc][1],     aPh[kc][0], aPl[kc][0]);
            splitpack(c_[2 * kc][2],     c_[2 * kc][3],     aPh[kc][1], aPl[kc][1]);
            splitpack(c_[2 * kc + 1][0], c_[2 * kc + 1][1], aPh[kc][2], aPl[kc][2]);
            splitpack(c_[2 * kc + 1][2], c_[2 * kc + 1][3], aPh[kc][3], aPl[kc][3]);
        }

#pragma unroll
        for (int nt = 0; nt < 8; nt += 2) {
#pragma unroll
            for (int kc = 0; kc < 4; kc++) {
                const int vr = kc * 16 + (lane & 15);
                const int nn = (nt + (lane >> 4)) * 8;
                uint32_t h0, h1, h2, h3, v0, v1, v2, v3;
                ldsm_x4_trans(h0, h1, h2, h3, &sVh[vr * 72 + nn]);
                ldsm_x4_trans(v0, v1, v2, v3, &sVl[vr * 72 + nn]);
                mma_bf16(O[nt], aPh[kc], h0, h1);
                mma_bf16(O[nt], aPh[kc], v0, v1);
                mma_bf16(O[nt], aPl[kc], h0, h1);
                mma_bf16(O[nt + 1], aPh[kc], h2, h3);
                mma_bf16(O[nt + 1], aPh[kc], v2, v3);
                mma_bf16(O[nt + 1], aPl[kc], h2, h3);
            }
        }
        __syncthreads();
    }

    l0 += __shfl_xor_sync(0xFFFFFFFFu, l0, 1);
    l0 += __shfl_xor_sync(0xFFFFFFFFu, l0, 2);
    l1 += __shfl_xor_sync(0xFFFFFFFFu, l1, 1);
    l1 += __shfl_xor_sync(0xFFFFFFFFu, l1, 2);
    const float inv0 = 1.0f / l0, inv1 = 1.0f / l1;
#pragma unroll
    for (int nt = 0; nt < 8; nt++) {
        const int col = h * DH + nt * 8 + 2 * lm4;
        float2 o0 = make_float2(O[nt][0] * inv0, O[nt][1] * inv0);
        float2 o1 = make_float2(O[nt][2] * inv1, O[nt][3] * inv1);
        *(float2*)&g_ao[((size_t)(b * SS + qrow)) * DD + col] = o0;
        *(float2*)&g_ao[((size_t)(b * SS + qrow + 8)) * DD + col] = o1;
    }
}

// ---------------- launch ------------------------------------------------------
extern "C" void kernel_launch(void* const* d_in, const int* in_sizes, int n_in,
                              void* d_out, int out_size) {
    const float* x    = (const float*)d_in[0];
    const void*  mask = d_in[1];
    const float* bias = (const float*)d_in[2];
    const float* Wqkv = (const float*)d_in[3];
    const float* bqkv = (const float*)d_in[4];
    const float* Wout = (const float*)d_in[5];
    const float* bout = (const float*)d_in[6];
    float* out = (float*)d_out;

    float *qkv = nullptr, *ao = nullptr;
    cudaGetSymbolAddress((void**)&qkv, g_qkv);
    cudaGetSymbolAddress((void**)&ao, g_ao);

    cudaFuncSetAttribute(flash_kernel,
                         cudaFuncAttributeMaxDynamicSharedMemorySize, FLASH_SMEM);

    detect_mask_kind_kernel<<<1, 256>>>((const unsigned int*)mask);

    // qkv = x @ W_qkv + b_qkv
    mma_gemm_bias_kernel<<<dim3(24, 64), 128>>>(x, Wqkv, bqkv, qkv, BB * SS, 3 * DD, DD);

    // head split + RoPE + hi/lo presplit of K,V
    rope_split_kernel<<<(BB * SS * HH * 32) / 256, 256>>>();

    // biasT + mask -> bf16
    biast3_kernel<<<dim3(SS / 512, SS, BB), 256>>>(bias, mask);

    // fused attention
    flash_kernel<<<dim3(SS / 64, BB * HH), 128, FLASH_SMEM>>>();

    // out = a_out @ W_out + b_out
    mma_gemm_bias_kernel<<<dim3(8, 64), 128>>>(ao, Wout, bout, out, BB * SS, DD, DD);
}